// round 3
// baseline (speedup 1.0000x reference)
#include <cuda_runtime.h>
#include <cuda_bf16.h>

// Problem constants (fixed by dataset)
#define DIM   128
#define MAXN  50000

typedef unsigned long long ull;

// Scratch: device globals (no allocation allowed).
__device__ __align__(16) float g_agg[MAXN * DIM];     // 25.6 MB
__device__ __align__(16) float g_cnt[MAXN];
__device__ __align__(16) float g_wcat[2 * DIM * DIM]; // W_cat[k][n], k in [0,256)
__device__ int g_is64;                                 // edge_index dtype flag

// ---------------------------------------------------------------------------
// Helpers: packed f32x2 FMA (sm_103a)
// ---------------------------------------------------------------------------
__device__ __forceinline__ ull pk2(float lo, float hi) {
    ull r;
    asm("mov.b64 %0, {%1, %2};" : "=l"(r) : "f"(lo), "f"(hi));
    return r;
}
__device__ __forceinline__ void upk2(float& lo, float& hi, ull v) {
    asm("mov.b64 {%0, %1}, %2;" : "=f"(lo), "=f"(hi) : "l"(v));
}
__device__ __forceinline__ void ffma2(ull& d, ull a, ull b) {
    asm("fma.rn.f32x2 %0, %1, %2, %0;" : "+l"(d) : "l"(a), "l"(b));
}

// ---------------------------------------------------------------------------
// Kernel 0: detect edge_index dtype. If the buffer is int64, every probed
// value (index into [0,N)) fits in 32 bits. If it is int32 misread as int64,
// the high word is a random index -> value >= 2^32 almost surely.
// ---------------------------------------------------------------------------
__global__ void detect_dtype_kernel(const void* ei_raw, int E, int N) {
    __shared__ int ok;
    if (threadIdx.x == 0) ok = 1;
    __syncthreads();
    const long long* e64 = (const long long*)ei_raw;
    int probe = (E < 1024) ? E : 1024;
    for (int i = threadIdx.x; i < probe; i += blockDim.x) {
        long long v = e64[i];
        if (v < 0 || v >= (long long)N) atomicExch(&ok, 0);
    }
    __syncthreads();
    if (threadIdx.x == 0) g_is64 = ok;
}

// ---------------------------------------------------------------------------
// Kernel 1: zero agg + cnt
// ---------------------------------------------------------------------------
__global__ void zero_kernel(int N) {
    int i = blockIdx.x * blockDim.x + threadIdx.x;
    int n4 = N * (DIM / 4);
    if (i < n4) reinterpret_cast<float4*>(g_agg)[i] = make_float4(0.f, 0.f, 0.f, 0.f);
    if (i < N) g_cnt[i] = 0.f;
}

// ---------------------------------------------------------------------------
// Kernel 2: build W_cat[k][n] = (k<128 ? W_l[n][k] : W_r[n][k-128])
// ---------------------------------------------------------------------------
__global__ void wcat_kernel(const float* __restrict__ Wl, const float* __restrict__ Wr) {
    int i = blockIdx.x * blockDim.x + threadIdx.x;
    if (i >= 2 * DIM * DIM) return;
    int k = i >> 7;         // 0..255
    int n = i & (DIM - 1);  // 0..127
    float v = (k < DIM) ? Wl[n * DIM + k] : Wr[n * DIM + (k - DIM)];
    g_wcat[i] = v;
}

// ---------------------------------------------------------------------------
// Kernel 3: edge scatter — one warp per edge.
// lane l handles float4 chunk l of the 128-float row.
// red.global.add.v4.f32 (no return) into g_agg[dst]; lane 0 bumps g_cnt[dst].
// Index dtype resolved at runtime via g_is64 (uniform branch).
// ---------------------------------------------------------------------------
__global__ void scatter_kernel(const void* __restrict__ ei_raw,
                               const float* __restrict__ x, int E, int N) {
    int e = blockIdx.x * (blockDim.x >> 5) + (threadIdx.x >> 5);
    if (e >= E) return;
    int lane = threadIdx.x & 31;

    long long s, d;
    if (g_is64) {
        const long long* ei = (const long long*)ei_raw;
        s = __ldg(&ei[e]);
        d = __ldg(&ei[E + e]);
    } else {
        const int* ei = (const int*)ei_raw;
        s = __ldg(&ei[e]);
        d = __ldg(&ei[E + e]);
    }
    // Safety: never fault on a bad index.
    if ((ull)s >= (ull)N || (ull)d >= (ull)N) return;

    const float4* xr = reinterpret_cast<const float4*>(x + (size_t)s * DIM);
    float4 v = xr[lane];
    float* p = g_agg + (size_t)d * DIM + lane * 4;
    asm volatile("red.global.add.v4.f32 [%0], {%1, %2, %3, %4};"
                 :: "l"(p), "f"(v.x), "f"(v.y), "f"(v.z), "f"(v.w) : "memory");
    if (lane == 0) {
        asm volatile("red.global.add.f32 [%0], %1;"
                     :: "l"(g_cnt + d), "f"(1.0f) : "memory");
    }
}

// ---------------------------------------------------------------------------
// Kernel 4: fused GEMM (A = [mean | x], W_cat) + bias + LayerNorm + ReLU
// Block: 256 threads, tile 128 rows x 128 cols. Thread (tx,ty) -> 8x8 micro-tile.
// f32x2 packed FMAs for 2x fp32 throughput.
// ---------------------------------------------------------------------------
#define BM   128
#define BK   32
#define PADA 136   // 136*4B stride: 16B-aligned, 4-way max store conflict

__global__ __launch_bounds__(256, 2)
void gemm_ln_kernel(const float* __restrict__ x,
                    const float* __restrict__ bl,
                    const float* __restrict__ gamma,
                    const float* __restrict__ beta,
                    float* __restrict__ out, int N) {
    __shared__ __align__(16) float As[BK * PADA];
    __shared__ __align__(16) float Ws[BK * DIM];
    __shared__ float sInv[BM];

    int tid = threadIdx.x;
    int row0 = blockIdx.x * BM;
    int tx = tid & 15;   // col group: cols tx*8 .. tx*8+7
    int ty = tid >> 4;   // row group: rows ty*8 .. ty*8+7

    if (tid < BM) {
        int r = row0 + tid;
        float c = (r < N) ? g_cnt[r] : 1.f;
        sInv[tid] = 1.f / fmaxf(c, 1.f);
    }

    ull acc[8][4];
#pragma unroll
    for (int r = 0; r < 8; ++r)
#pragma unroll
        for (int p = 0; p < 4; ++p) acc[r][p] = 0ull;

    for (int kt = 0; kt < 8; ++kt) {
        int k0 = kt * BK;
        bool isMean = (k0 < DIM);
        const float* src = isMean ? g_agg : x;
        int koff = isMean ? k0 : (k0 - DIM);

        __syncthreads();
        // A tile: As[c][r] (k-major), with mean = agg * invcnt folded in
        for (int i = tid; i < BM * BK; i += 256) {
            int r = i >> 5;
            int c = i & 31;
            int gr = row0 + r;
            float v = 0.f;
            if (gr < N) {
                v = src[(size_t)gr * DIM + koff + c];
                if (isMean) v *= sInv[r];
            }
            As[c * PADA + r] = v;
        }
        // W tile: Ws[c][n] straight copy (already k-major in g_wcat)
        for (int i = tid; i < BK * DIM; i += 256) {
            Ws[i] = g_wcat[k0 * DIM + i];
        }
        __syncthreads();

#pragma unroll 8
        for (int kk = 0; kk < BK; ++kk) {
            const float4* wr = reinterpret_cast<const float4*>(Ws + kk * DIM);
            float4 w0 = wr[tx * 2];
            float4 w1 = wr[tx * 2 + 1];
            const float4* ar = reinterpret_cast<const float4*>(As + kk * PADA);
            float4 a0 = ar[ty * 2];
            float4 a1 = ar[ty * 2 + 1];
            ull wp0 = pk2(w0.x, w0.y);
            ull wp1 = pk2(w0.z, w0.w);
            ull wp2 = pk2(w1.x, w1.y);
            ull wp3 = pk2(w1.z, w1.w);
            float av[8] = {a0.x, a0.y, a0.z, a0.w, a1.x, a1.y, a1.z, a1.w};
#pragma unroll
            for (int r = 0; r < 8; ++r) {
                ull ap = pk2(av[r], av[r]);
                ffma2(acc[r][0], ap, wp0);
                ffma2(acc[r][1], ap, wp1);
                ffma2(acc[r][2], ap, wp2);
                ffma2(acc[r][3], ap, wp3);
            }
        }
    }

    // -------- epilogue: bias + LayerNorm + ReLU --------
    float h[8][8];
#pragma unroll
    for (int r = 0; r < 8; ++r)
#pragma unroll
        for (int p = 0; p < 4; ++p) upk2(h[r][2 * p], h[r][2 * p + 1], acc[r][p]);

    const float4* bl4 = reinterpret_cast<const float4*>(bl);
    const float4* g4  = reinterpret_cast<const float4*>(gamma);
    const float4* be4 = reinterpret_cast<const float4*>(beta);
    float4 bb0 = bl4[tx * 2], bb1 = bl4[tx * 2 + 1];
    float4 gg0 = g4[tx * 2],  gg1 = g4[tx * 2 + 1];
    float4 ee0 = be4[tx * 2], ee1 = be4[tx * 2 + 1];
    float bb[8] = {bb0.x, bb0.y, bb0.z, bb0.w, bb1.x, bb1.y, bb1.z, bb1.w};
    float gg[8] = {gg0.x, gg0.y, gg0.z, gg0.w, gg1.x, gg1.y, gg1.z, gg1.w};
    float ee[8] = {ee0.x, ee0.y, ee0.z, ee0.w, ee1.x, ee1.y, ee1.z, ee1.w};

    float4* out4 = reinterpret_cast<float4*>(out);

#pragma unroll
    for (int r = 0; r < 8; ++r) {
#pragma unroll
        for (int c = 0; c < 8; ++c) h[r][c] += bb[c];

        // mean over 128 cols: local 8 + shfl over 16 tx lanes (lane bits 0..3)
        float s = 0.f;
#pragma unroll
        for (int c = 0; c < 8; ++c) s += h[r][c];
#pragma unroll
        for (int m = 1; m < 16; m <<= 1) s += __shfl_xor_sync(0xffffffffu, s, m);
        float mu = s * (1.0f / 128.0f);

        float q = 0.f;
#pragma unroll
        for (int c = 0; c < 8; ++c) {
            float d = h[r][c] - mu;
            q += d * d;
        }
#pragma unroll
        for (int m = 1; m < 16; m <<= 1) q += __shfl_xor_sync(0xffffffffu, q, m);
        float rstd = rsqrtf(q * (1.0f / 128.0f) + 1e-5f);

        int grow = row0 + ty * 8 + r;
        if (grow < N) {
            float o[8];
#pragma unroll
            for (int c = 0; c < 8; ++c) {
                float v = fmaf((h[r][c] - mu) * rstd, gg[c], ee[c]);
                o[c] = fmaxf(v, 0.f);
            }
            float4 o0 = make_float4(o[0], o[1], o[2], o[3]);
            float4 o1 = make_float4(o[4], o[5], o[6], o[7]);
            out4[(size_t)grow * 32 + tx * 2]     = o0;
            out4[(size_t)grow * 32 + tx * 2 + 1] = o1;
        }
    }
}

// ---------------------------------------------------------------------------
// Launch
// ---------------------------------------------------------------------------
extern "C" void kernel_launch(void* const* d_in, const int* in_sizes, int n_in,
                              void* d_out, int out_size) {
    const float* x      = (const float*)d_in[0];
    const void*  ei     = d_in[1];                 // int32 or int64, detected on device
    const float* Wl     = (const float*)d_in[2];
    const float* bl     = (const float*)d_in[3];
    const float* Wr     = (const float*)d_in[4];
    const float* gamma  = (const float*)d_in[5];
    const float* beta   = (const float*)d_in[6];
    float* out          = (float*)d_out;

    int N = in_sizes[0] / DIM;
    int E = in_sizes[1] / 2;

    // 0) dtype probe (writes g_is64)
    detect_dtype_kernel<<<1, 256>>>(ei, E, N);
    // 1) zero scratch
    {
        int total = N * (DIM / 4);
        int blocks = (total + 255) / 256;
        zero_kernel<<<blocks, 256>>>(N);
    }
    // 2) W_cat
    {
        int total = 2 * DIM * DIM;
        wcat_kernel<<<(total + 255) / 256, 256>>>(Wl, Wr);
    }
    // 3) scatter (1 warp per edge, 8 warps per block)
    {
        int blocks = (E + 7) / 8;
        scatter_kernel<<<blocks, 256>>>(ei, x, E, N);
    }
    // 4) fused GEMM + LN + ReLU
    {
        int blocks = (N + BM - 1) / BM;
        gemm_ln_kernel<<<blocks, 256>>>(x, bl, gamma, beta, out, N);
    }
}